// round 15
// baseline (speedup 1.0000x reference)
#include <cuda_runtime.h>
#include <cuda_fp16.h>
#include <cstdint>

// Problem constants
#define BATCH 4
#define SEQ   2048
#define DIM   1024
#define HEADS 16
#define HD    64
#define ROWS  (BATCH * SEQ)          // 8192
#define QKV_N (HEADS * 3 * HD)       // 3072
#define BHSD  (BATCH * HEADS * SEQ * HD)
#define Q_SCALE (0.125f * 1.4426950408889634f)

// -------- scratch (static device globals; no allocation allowed) --------
__device__ __half g_xn_hi[ROWS * DIM];
__device__ __half g_wq_hi[DIM * QKV_N];   // q-columns pre-scaled by Q_SCALE
__device__ __half g_wo_hi[DIM * DIM];
__device__ float  g_bq_s[QKV_N];          // bias, q part pre-scaled
__device__ __half g_qh[BHSD];   // [b,h,s,d] fp16 (pre-scaled via weights)
__device__ __half g_kh[BHSD];
__device__ __half g_vh[BHSD];
__device__ __half g_y_hi[ROWS * DIM];   // attn out [b,s,h,d]

// ============================ helpers ============================
__device__ __forceinline__ uint32_t s2u(const void* p) {
    return (uint32_t)__cvta_generic_to_shared(p);
}
__device__ __forceinline__ void ldsm4(uint32_t* r, uint32_t addr) {
    asm volatile("ldmatrix.sync.aligned.m8n8.x4.shared.b16 {%0,%1,%2,%3}, [%4];\n"
                 : "=r"(r[0]), "=r"(r[1]), "=r"(r[2]), "=r"(r[3]) : "r"(addr));
}
__device__ __forceinline__ void ldsm4t(uint32_t* r, uint32_t addr) {
    asm volatile("ldmatrix.sync.aligned.m8n8.x4.trans.shared.b16 {%0,%1,%2,%3}, [%4];\n"
                 : "=r"(r[0]), "=r"(r[1]), "=r"(r[2]), "=r"(r[3]) : "r"(addr));
}
__device__ __forceinline__ void mma_f16(float* c, const uint32_t* a, const uint32_t* b) {
    asm volatile(
        "mma.sync.aligned.m16n8k16.row.col.f32.f16.f16.f32 "
        "{%0,%1,%2,%3}, {%4,%5,%6,%7}, {%8,%9}, {%0,%1,%2,%3};\n"
        : "+f"(c[0]), "+f"(c[1]), "+f"(c[2]), "+f"(c[3])
        : "r"(a[0]), "r"(a[1]), "r"(a[2]), "r"(a[3]), "r"(b[0]), "r"(b[1]));
}
__device__ __forceinline__ void cp16(uint32_t smem_dst, const void* gmem_src) {
    asm volatile("cp.async.cg.shared.global [%0], [%1], 16;\n"
                 :: "r"(smem_dst), "l"(gmem_src));
}
__device__ __forceinline__ void cp_commit() {
    asm volatile("cp.async.commit_group;\n");
}
template <int N>
__device__ __forceinline__ void cp_wait() {
    asm volatile("cp.async.wait_group %0;\n" :: "n"(N));
}
__device__ __forceinline__ float ex2(float x) {
    float r;
    asm("ex2.approx.f32 %0, %1;" : "=f"(r) : "f"(x));
    return r;
}

// ============================ LayerNorm -> fp16 ============================
__global__ void __launch_bounds__(256) ln_kernel(
    const float* __restrict__ x,
    const float* __restrict__ gamma,
    const float* __restrict__ beta,
    __half* __restrict__ out_hi)
{
    int row = blockIdx.x;
    int t = threadIdx.x;
    const float4* xr = reinterpret_cast<const float4*>(x + (size_t)row * DIM);
    float4 v = xr[t];
    float s1 = v.x + v.y + v.z + v.w;
    float s2 = v.x*v.x + v.y*v.y + v.z*v.z + v.w*v.w;
    #pragma unroll
    for (int o = 16; o > 0; o >>= 1) {
        s1 += __shfl_xor_sync(0xffffffffu, s1, o);
        s2 += __shfl_xor_sync(0xffffffffu, s2, o);
    }
    __shared__ float r1[8], r2[8];
    __shared__ float sh_mu, sh_rstd;
    if ((t & 31) == 0) { r1[t >> 5] = s1; r2[t >> 5] = s2; }
    __syncthreads();
    if (t == 0) {
        float a = 0.f, b = 0.f;
        #pragma unroll
        for (int i = 0; i < 8; i++) { a += r1[i]; b += r2[i]; }
        float mu  = a * (1.0f / DIM);
        float var = b * (1.0f / DIM) - mu * mu;
        sh_mu = mu;
        sh_rstd = rsqrtf(var + 1e-6f);
    }
    __syncthreads();
    float mu = sh_mu, rstd = sh_rstd;
    float4 g = reinterpret_cast<const float4*>(gamma)[t];
    float4 b4 = reinterpret_cast<const float4*>(beta)[t];
    float o0 = (v.x - mu) * rstd * g.x + b4.x;
    float o1 = (v.y - mu) * rstd * g.y + b4.y;
    float o2 = (v.z - mu) * rstd * g.z + b4.z;
    float o3 = (v.w - mu) * rstd * g.w + b4.w;
    __half2 ha = __floats2half2_rn(o0, o1);
    __half2 hb = __floats2half2_rn(o2, o3);
    size_t base = (size_t)row * DIM + t * 4;
    *reinterpret_cast<__half2*>(&out_hi[base])     = ha;
    *reinterpret_cast<__half2*>(&out_hi[base + 2]) = hb;
}

// ============================ weight/bias prep (fused, q-scale folded) ============================
__global__ void __launch_bounds__(256) prep_kernel(
    const float* __restrict__ wq, const float* __restrict__ wo,
    const float* __restrict__ bq,
    __half* __restrict__ wq_h, __half* __restrict__ wo_h,
    float* __restrict__ bq_s)
{
    const int n1 = DIM * QKV_N;
    const int n2 = DIM * DIM;
    int stride = gridDim.x * blockDim.x;
    for (int idx = blockIdx.x * blockDim.x + threadIdx.x;
         idx < n1 + n2 + QKV_N; idx += stride) {
        if (idx < n1) {
            int col = idx % QKV_N;
            float sc = ((col % 192) < 64) ? Q_SCALE : 1.0f;
            wq_h[idx] = __float2half_rn(wq[idx] * sc);
        } else if (idx < n1 + n2) {
            wo_h[idx - n1] = __float2half_rn(wo[idx - n1]);
        } else {
            int col = idx - n1 - n2;
            float sc = ((col % 192) < 64) ? Q_SCALE : 1.0f;
            bq_s[col] = bq[col] * sc;
        }
    }
}

// ============================ fp16 single-pass MMA GEMM 128x128, 32-K slices, 3-stage ============================
// Warp tile 32x64 (4x2 layout), 256 threads, 2 CTA/SM.
// MODE 0: QKV — scatter fp16 into q/k/v ([b,h,s,d]); scales pre-folded.
// MODE 1: fp32 C.
#define GA_STRIDE 40                        // halves per A row (32 data + 8 pad)
#define GB_STRIDE 136                       // halves per B row (128 data + 8 pad)
#define GA_BYTES  (128 * GA_STRIDE * 2)     // 10240
#define GB_BYTES  (32 * GB_STRIDE * 2)      // 8704
#define GSTAGE    (GA_BYTES + GB_BYTES)     // 18944
#define G_OFF_B   GA_BYTES
template <int MODE>
__global__ void __launch_bounds__(256, 2) mma_gemm(
    const __half* __restrict__ Ag,
    const __half* __restrict__ Bg,
    const float* __restrict__ bias,
    float* __restrict__ Cout,
    int M, int N, int K,
    __half* __restrict__ qh, __half* __restrict__ kh, __half* __restrict__ vh)
{
    extern __shared__ __align__(16) char smem[];
    uint32_t smem_base = s2u(smem);

    int tid = threadIdx.x;
    int lane = tid & 31;
    int wid = tid >> 5;
    int wm = wid & 3;
    int wn = wid >> 2;
    int m0 = blockIdx.y * 128;
    int n0 = blockIdx.x * 128;

    int arow = tid >> 1;
    int acol = (tid & 1) * 16;
    int brow = tid >> 3;
    int bcol = (tid & 7) * 16;

    const __half* pA = Ag + (size_t)(m0 + arow) * K + acol;
    const __half* pB = Bg + (size_t)brow * N + n0 + bcol;
    uint32_t aoff = (arow * GA_STRIDE + acol) * 2;
    uint32_t boff = (brow * GB_STRIDE + bcol) * 2;

    float acc[2][8][4];
    #pragma unroll
    for (int i = 0; i < 2; i++)
        #pragma unroll
        for (int j = 0; j < 8; j++)
            #pragma unroll
            for (int e = 0; e < 4; e++) acc[i][j][e] = 0.f;

    int niter = K / 32;

    auto issue = [&](int kt, int s) {
        uint32_t st = smem_base + s * GSTAGE;
        int ko = kt * 32;
        const __half* a = pA + ko;
        const __half* b = pB + (size_t)ko * N;
        cp16(st + aoff,              a);
        cp16(st + aoff + 16,         a + 8);
        cp16(st + G_OFF_B + boff,      b);
        cp16(st + G_OFF_B + boff + 16, b + 8);
        cp_commit();
    };

    issue(0, 0);
    issue(1, 1);

    int lrow = lane & 15;
    int lcol = (lane >> 4) * 8;
    uint32_t baseA[2];
    #pragma unroll
    for (int i = 0; i < 2; i++)
        baseA[i] = smem_base + ((wm * 32 + i * 16 + lrow) * GA_STRIDE + lcol) * 2;
    uint32_t baseB[4];
    #pragma unroll
    for (int jj = 0; jj < 4; jj++)
        baseB[jj] = smem_base + G_OFF_B + (lrow * GB_STRIDE + wn * 64 + jj * 16 + lcol) * 2;

    int s = 0;
    for (int kt = 0; kt < niter; kt++) {
        if (kt + 1 < niter) cp_wait<1>();
        else                cp_wait<0>();
        __syncthreads();

        if (kt + 2 < niter) {
            int s2 = s + 2; if (s2 >= 3) s2 -= 3;
            issue(kt + 2, s2);
        }

        uint32_t offS = (uint32_t)(s * GSTAGE);
        #pragma unroll
        for (int ss = 0; ss < 2; ss++) {
            uint32_t aSub = offS + ss * 32;
            uint32_t bSub = offS + ss * 16 * GB_STRIDE * 2;

            uint32_t ah[2][4], bb[8][2];
            #pragma unroll
            for (int i = 0; i < 2; i++)
                ldsm4(ah[i], baseA[i] + aSub);
            #pragma unroll
            for (int jj = 0; jj < 4; jj++) {
                uint32_t r[4];
                ldsm4t(r, baseB[jj] + bSub);
                bb[jj * 2][0] = r[0]; bb[jj * 2][1] = r[1];
                bb[jj * 2 + 1][0] = r[2]; bb[jj * 2 + 1][1] = r[3];
            }
            #pragma unroll
            for (int i = 0; i < 2; i++)
                #pragma unroll
                for (int j = 0; j < 8; j++)
                    mma_f16(acc[i][j], ah[i], bb[j]);
        }
        s++; if (s == 3) s = 0;
    }

    int gid = lane >> 2, tig = lane & 3;
    #pragma unroll
    for (int i = 0; i < 2; i++) {
        #pragma unroll
        for (int j = 0; j < 8; j++) {
            int n = n0 + wn * 64 + j * 8 + 2 * tig;
            if (MODE == 0) {
                int hq = n / 192;
                int f = n - hq * 192;
                __half* dst;
                int off;
                if (f < 64)       { dst = qh; off = f; }
                else if (f < 128) { dst = kh; off = f - 64; }
                else              { dst = vh; off = f - 128; }
                float b0 = bias[n], b1 = bias[n + 1];
                #pragma unroll
                for (int rh = 0; rh < 2; rh++) {
                    int m = m0 + wm * 32 + i * 16 + gid + rh * 8;
                    float v0 = acc[i][j][rh * 2 + 0] + b0;
                    float v1 = acc[i][j][rh * 2 + 1] + b1;
                    int bb2 = m >> 11;
                    int ss2 = m & 2047;
                    size_t base = (((size_t)(bb2 * HEADS + hq)) * SEQ + ss2) * HD;
                    __half2 h2 = __floats2half2_rn(v0, v1);
                    *reinterpret_cast<uint32_t*>(&dst[base + off]) =
                        *reinterpret_cast<uint32_t*>(&h2);
                }
            } else {
                float b0 = bias[n], b1 = bias[n + 1];
                #pragma unroll
                for (int rh = 0; rh < 2; rh++) {
                    int m = m0 + wm * 32 + i * 16 + gid + rh * 8;
                    float v0 = acc[i][j][rh * 2 + 0] + b0;
                    float v1 = acc[i][j][rh * 2 + 1] + b1;
                    *reinterpret_cast<float2*>(&Cout[(size_t)m * N + n]) = make_float2(v0, v1);
                }
            }
        }
    }
}

// ============================ Tensor-core flash attention ============================
// 128-key stages (2x64 halves per barrier), log2-domain MUFU softmax,
// deferred l-sum reduction (epilogue-only shuffle).
#define KV2 (128 * 72)
__global__ void __launch_bounds__(256) attn_mma_kernel(
    const __half* __restrict__ qh_g,
    const __half* __restrict__ kh_g,
    const __half* __restrict__ vh_g,
    __half* __restrict__ y_hi)
{
    extern __shared__ __half smb[];
    __half* sQh = smb;                      // [128][72]
    __half* sKh = sQh + 128 * 72;           // [2][128][72]
    __half* sVh = sKh + 2 * KV2;            // [2][128][72]

    int bh = blockIdx.x;
    int qt = (gridDim.y - 1) - blockIdx.y;   // heavy tiles first
    int tid = threadIdx.x;
    int lane = tid & 31;
    int w = tid >> 5;
    int gid = lane >> 2, tig = lane & 3;
    int lrow = lane & 15, lcol = (lane >> 4) * 8;

    int q0 = qt * 128;
    const size_t bhoff = (size_t)bh * SEQ * HD;

    int kvr = tid >> 3;                 // 0..31, 4 rows each via +32
    int kvd = (tid & 7) * 8;
    auto issue_kv = [&](int kt, int st) {
        int c0 = kt * 128;
        size_t base = st * KV2;
        #pragma unroll
        for (int i = 0; i < 4; i++) {
            int r = kvr + i * 32;
            size_t g = bhoff + (size_t)(c0 + r) * HD + kvd;
            size_t sm = base + r * 72 + kvd;
            cp16(s2u(&sKh[sm]), &kh_g[g]);
            cp16(s2u(&sVh[sm]), &vh_g[g]);
        }
        cp_commit();
    };

    int ktmax = qt;                     // 128-key tiles, inclusive (diagonal)
    issue_kv(0, 0);

    #pragma unroll
    for (int i = 0; i < 4; i++) {
        int chunk = tid + i * 256;
        int r = chunk >> 3, d8 = (chunk & 7) * 8;
        size_t g = bhoff + (size_t)(q0 + r) * HD + d8;
        *reinterpret_cast<uint4*>(&sQh[r * 72 + d8]) = *reinterpret_cast<const uint4*>(&qh_g[g]);
    }
    __syncthreads();

    uint32_t qfh[4][4];
    #pragma unroll
    for (int kk = 0; kk < 4; kk++)
        ldsm4(qfh[kk], s2u(&sQh[(w * 16 + lrow) * 72 + kk * 16 + lcol]));

    float m_r[2] = {-1e30f, -1e30f};
    float l_r[2] = {0.f, 0.f};          // per-thread PARTIAL sums (reduced in epilogue)
    float o[8][4];
    #pragma unroll
    for (int j = 0; j < 8; j++)
        #pragma unroll
        for (int c = 0; c < 4; c++) o[j][c] = 0.f;

    for (int kt = 0; kt <= ktmax; kt++) {
        int st = kt & 1;
        uint32_t offKV = (uint32_t)(st * KV2 * 2);

        cp_wait<0>();
        __syncthreads();   // stage st ready; all warps done reading other stage

        if (kt < ktmax) issue_kv(kt + 1, (kt + 1) & 1);

        #pragma unroll
        for (int h = 0; h < 2; h++) {
            int c0 = kt * 128 + h * 64;
            uint32_t offH = offKV + (uint32_t)(h * 64 * 72 * 2);

            float s[8][4];
            #pragma unroll
            for (int j = 0; j < 8; j++)
                #pragma unroll
                for (int c = 0; c < 4; c++) s[j][c] = 0.f;

            #pragma unroll
            for (int kk = 0; kk < 4; kk++) {
                #pragma unroll
                for (int g2 = 0; g2 < 4; g2++) {
                    uint32_t rh[4];
                    ldsm4(rh, s2u(&sKh[(g2 * 16 + lrow) * 72 + kk * 16 + lcol]) + offH);
                    uint32_t b0h[2] = {rh[0], rh[2]}, b1h[2] = {rh[1], rh[3]};
                    mma_f16(s[g2 * 2],     qfh[kk], b0h);
                    mma_f16(s[g2 * 2 + 1], qfh[kk], b1h);
                }
            }

            if (kt == ktmax) {  // diagonal 128-block: mask both halves
                int row0 = q0 + w * 16 + gid;
                #pragma unroll
                for (int j = 0; j < 8; j++) {
                    int col = c0 + j * 8 + 2 * tig;
                    if (col     > row0)     s[j][0] = -1e30f;
                    if (col + 1 > row0)     s[j][1] = -1e30f;
                    if (col     > row0 + 8) s[j][2] = -1e30f;
                    if (col + 1 > row0 + 8) s[j][3] = -1e30f;
                }
            }

            // ---- online softmax (log2 domain, deferred l reduction) ----
            float mx0 = -1e30f, mx1 = -1e30f;
            #pragma unroll
            for (int j = 0; j < 8; j++) {
                mx0 = fmaxf(mx0, fmaxf(s[j][0], s[j][1]));
                mx1 = fmaxf(mx1, fmaxf(s[j][2], s[j][3]));
            }
            mx0 = fmaxf(mx0, __shfl_xor_sync(0xffffffffu, mx0, 1));
            mx0 = fmaxf(mx0, __shfl_xor_sync(0xffffffffu, mx0, 2));
            mx1 = fmaxf(mx1, __shfl_xor_sync(0xffffffffu, mx1, 1));
            mx1 = fmaxf(mx1, __shfl_xor_sync(0xffffffffu, mx1, 2));
            float mn0 = fmaxf(m_r[0], mx0);
            float mn1 = fmaxf(m_r[1], mx1);
            float corr0 = ex2(m_r[0] - mn0);
            float corr1 = ex2(m_r[1] - mn1);
            float rs0 = 0.f, rs1 = 0.f;
            #pragma unroll
            for (int j = 0; j < 8; j++) {
                s[j][0] = ex2(s[j][0] - mn0); rs0 += s[j][0];
                s[j][1] = ex2(s[j][1] - mn0); rs0 += s[j][1];
                s[j][2] = ex2(s[j][2] - mn1); rs1 += s[j][2];
                s[j][3] = ex2(s[j][3] - mn1); rs1 += s[j][3];
            }
            l_r[0] = l_r[0] * corr0 + rs0;   // partial (own columns only)
            l_r[1] = l_r[1] * corr1 + rs1;
            m_r[0] = mn0; m_r[1] = mn1;
            #pragma unroll
            for (int j = 0; j < 8; j++) {
                o[j][0] *= corr0; o[j][1] *= corr0;
                o[j][2] *= corr1; o[j][3] *= corr1;
            }

            // ---- O += P V (P fp16) ----
            #pragma unroll
            for (int kk = 0; kk < 4; kk++) {
                uint32_t ph[4];
                __half2 p0 = __floats2half2_rn(s[2 * kk][0],     s[2 * kk][1]);
                __half2 p1 = __floats2half2_rn(s[2 * kk][2],     s[2 * kk][3]);
                __half2 p2 = __floats2half2_rn(s[2 * kk + 1][0], s[2 * kk + 1][1]);
                __half2 p3 = __floats2half2_rn(s[2 * kk + 1][2], s[2 * kk + 1][3]);
                ph[0] = *reinterpret_cast<uint32_t*>(&p0);
                ph[1] = *reinterpret_cast<uint32_t*>(&p1);
                ph[2] = *reinterpret_cast<uint32_t*>(&p2);
                ph[3] = *reinterpret_cast<uint32_t*>(&p3);
                #pragma unroll
                for (int g2 = 0; g2 < 4; g2++) {
                    uint32_t rvh[4];
                    ldsm4t(rvh, s2u(&sVh[(kk * 16 + lrow) * 72 + g2 * 16 + lcol]) + offH);
                    uint32_t bh0[2] = {rvh[0], rvh[1]}, bh1[2] = {rvh[2], rvh[3]};
                    mma_f16(o[g2 * 2],     ph, bh0);
                    mma_f16(o[g2 * 2 + 1], ph, bh1);
                }
            }
        }
    }

    // epilogue: reduce deferred l across the 4 threads of each row, then write
    float l0 = l_r[0], l1 = l_r[1];
    l0 += __shfl_xor_sync(0xffffffffu, l0, 1);
    l0 += __shfl_xor_sync(0xffffffffu, l0, 2);
    l1 += __shfl_xor_sync(0xffffffffu, l1, 1);
    l1 += __shfl_xor_sync(0xffffffffu, l1, 2);

    int b = bh >> 4, hh = bh & 15;
    float inv0 = 1.0f / l0;
    float inv1 = 1.0f / l1;
    #pragma unroll
    for (int h2 = 0; h2 < 2; h2++) {
        int srow = q0 + w * 16 + gid + h2 * 8;
        float inv = h2 ? inv1 : inv0;
        size_t base = (((size_t)(b * SEQ + srow)) * HEADS + hh) * HD;
        #pragma unroll
        for (int j = 0; j < 8; j++) {
            float a = o[j][h2 * 2 + 0] * inv;
            float c = o[j][h2 * 2 + 1] * inv;
            __half2 h2v = __floats2half2_rn(a, c);
            int d = j * 8 + 2 * tig;
            *reinterpret_cast<uint32_t*>(&y_hi[base + d]) = *reinterpret_cast<uint32_t*>(&h2v);
        }
    }
}

// ============================ launch ============================
extern "C" void kernel_launch(void* const* d_in, const int* in_sizes, int n_in,
                              void* d_out, int out_size)
{
    const float* x        = (const float*)d_in[0];
    const float* ln_scale = (const float*)d_in[2];
    const float* ln_bias  = (const float*)d_in[3];
    const float* w_qkv    = (const float*)d_in[4];
    const float* b_qkv    = (const float*)d_in[5];
    const float* w_out    = (const float*)d_in[6];
    const float* b_out    = (const float*)d_in[7];
    float* out = (float*)d_out;

    __half *xn_hi, *wq_hi, *wo_hi, *y_hi;
    __half *qh, *kh, *vh;
    float* bq_s;
    cudaGetSymbolAddress((void**)&xn_hi, g_xn_hi);
    cudaGetSymbolAddress((void**)&wq_hi, g_wq_hi);
    cudaGetSymbolAddress((void**)&wo_hi, g_wo_hi);
    cudaGetSymbolAddress((void**)&y_hi,  g_y_hi);
    cudaGetSymbolAddress((void**)&qh, g_qh);
    cudaGetSymbolAddress((void**)&kh, g_kh);
    cudaGetSymbolAddress((void**)&vh, g_vh);
    cudaGetSymbolAddress((void**)&bq_s, g_bq_s);

    // 1. LayerNorm -> fp16
    ln_kernel<<<ROWS, 256>>>(x, ln_scale, ln_bias, xn_hi);

    // 1b. fused weight/bias prep (q-scale folded)
    prep_kernel<<<768, 256>>>(w_qkv, w_out, b_qkv, wq_hi, wo_hi, bq_s);

    int gemm_smem = 3 * GSTAGE;   // 56832

    // 2. QKV projection -> q/k/v fp16 [b,h,s,d]
    {
        cudaFuncSetAttribute(mma_gemm<0>,
                             cudaFuncAttributeMaxDynamicSharedMemorySize, gemm_smem);
        dim3 grid(QKV_N / 128, ROWS / 128);  // (24, 64)
        mma_gemm<0><<<grid, 256, gemm_smem>>>(xn_hi, wq_hi, bq_s, nullptr,
                                              ROWS, QKV_N, DIM, qh, kh, vh);
    }

    // 3. tensor-core causal flash attention (128-key stages)
    {
        int smem = (128 * 72 + 4 * KV2) * sizeof(__half);  // 92160
        cudaFuncSetAttribute(attn_mma_kernel,
                             cudaFuncAttributeMaxDynamicSharedMemorySize, smem);
        dim3 grid(BATCH * HEADS, SEQ / 128);  // (64, 16)
        attn_mma_kernel<<<grid, 256, smem>>>(qh, kh, vh, y_hi);
    }

    // 4. output projection -> d_out
    {
        cudaFuncSetAttribute(mma_gemm<1>,
                             cudaFuncAttributeMaxDynamicSharedMemorySize, gemm_smem);
        dim3 grid(DIM / 128, ROWS / 128);    // (8, 64)
        mma_gemm<1><<<grid, 256, gemm_smem>>>(y_hi, wo_hi, b_out, out,
                                              ROWS, DIM, DIM,
                                              nullptr, nullptr, nullptr);
    }
}

// round 16
// speedup vs baseline: 1.0410x; 1.0410x over previous
#include <cuda_runtime.h>
#include <cuda_fp16.h>
#include <cstdint>

// Problem constants
#define BATCH 4
#define SEQ   2048
#define DIM   1024
#define HEADS 16
#define HD    64
#define ROWS  (BATCH * SEQ)          // 8192
#define QKV_N (HEADS * 3 * HD)       // 3072
#define BHSD  (BATCH * HEADS * SEQ * HD)
#define Q_SCALE (0.125f * 1.4426950408889634f)

// -------- scratch (static device globals; no allocation allowed) --------
__device__ __half g_xn_hi[ROWS * DIM];
__device__ __half g_wq_hi[DIM * QKV_N];   // q-columns pre-scaled by Q_SCALE
__device__ __half g_wo_hi[DIM * DIM];
__device__ float  g_bq_s[QKV_N];          // bias, q part pre-scaled
__device__ __half g_qh[BHSD];   // [b,h,s,d] fp16 (pre-scaled via weights)
__device__ __half g_kh[BHSD];
__device__ __half g_vh[BHSD];
__device__ __half g_y_hi[ROWS * DIM];   // attn out [b,s,h,d]

// ============================ helpers ============================
__device__ __forceinline__ uint32_t s2u(const void* p) {
    return (uint32_t)__cvta_generic_to_shared(p);
}
__device__ __forceinline__ void ldsm4(uint32_t* r, uint32_t addr) {
    asm volatile("ldmatrix.sync.aligned.m8n8.x4.shared.b16 {%0,%1,%2,%3}, [%4];\n"
                 : "=r"(r[0]), "=r"(r[1]), "=r"(r[2]), "=r"(r[3]) : "r"(addr));
}
__device__ __forceinline__ void ldsm4t(uint32_t* r, uint32_t addr) {
    asm volatile("ldmatrix.sync.aligned.m8n8.x4.trans.shared.b16 {%0,%1,%2,%3}, [%4];\n"
                 : "=r"(r[0]), "=r"(r[1]), "=r"(r[2]), "=r"(r[3]) : "r"(addr));
}
__device__ __forceinline__ void mma_f16(float* c, const uint32_t* a, const uint32_t* b) {
    asm volatile(
        "mma.sync.aligned.m16n8k16.row.col.f32.f16.f16.f32 "
        "{%0,%1,%2,%3}, {%4,%5,%6,%7}, {%8,%9}, {%0,%1,%2,%3};\n"
        : "+f"(c[0]), "+f"(c[1]), "+f"(c[2]), "+f"(c[3])
        : "r"(a[0]), "r"(a[1]), "r"(a[2]), "r"(a[3]), "r"(b[0]), "r"(b[1]));
}
__device__ __forceinline__ void cp16(uint32_t smem_dst, const void* gmem_src) {
    asm volatile("cp.async.cg.shared.global [%0], [%1], 16;\n"
                 :: "r"(smem_dst), "l"(gmem_src));
}
__device__ __forceinline__ void cp_commit() {
    asm volatile("cp.async.commit_group;\n");
}
template <int N>
__device__ __forceinline__ void cp_wait() {
    asm volatile("cp.async.wait_group %0;\n" :: "n"(N));
}
__device__ __forceinline__ float ex2(float x) {
    float r;
    asm("ex2.approx.f32 %0, %1;" : "=f"(r) : "f"(x));
    return r;
}

// ============================ LayerNorm -> fp16 ============================
__global__ void __launch_bounds__(256) ln_kernel(
    const float* __restrict__ x,
    const float* __restrict__ gamma,
    const float* __restrict__ beta,
    __half* __restrict__ out_hi)
{
    int row = blockIdx.x;
    int t = threadIdx.x;
    const float4* xr = reinterpret_cast<const float4*>(x + (size_t)row * DIM);
    float4 v = xr[t];
    float s1 = v.x + v.y + v.z + v.w;
    float s2 = v.x*v.x + v.y*v.y + v.z*v.z + v.w*v.w;
    #pragma unroll
    for (int o = 16; o > 0; o >>= 1) {
        s1 += __shfl_xor_sync(0xffffffffu, s1, o);
        s2 += __shfl_xor_sync(0xffffffffu, s2, o);
    }
    __shared__ float r1[8], r2[8];
    __shared__ float sh_mu, sh_rstd;
    if ((t & 31) == 0) { r1[t >> 5] = s1; r2[t >> 5] = s2; }
    __syncthreads();
    if (t == 0) {
        float a = 0.f, b = 0.f;
        #pragma unroll
        for (int i = 0; i < 8; i++) { a += r1[i]; b += r2[i]; }
        float mu  = a * (1.0f / DIM);
        float var = b * (1.0f / DIM) - mu * mu;
        sh_mu = mu;
        sh_rstd = rsqrtf(var + 1e-6f);
    }
    __syncthreads();
    float mu = sh_mu, rstd = sh_rstd;
    float4 g = reinterpret_cast<const float4*>(gamma)[t];
    float4 b4 = reinterpret_cast<const float4*>(beta)[t];
    float o0 = (v.x - mu) * rstd * g.x + b4.x;
    float o1 = (v.y - mu) * rstd * g.y + b4.y;
    float o2 = (v.z - mu) * rstd * g.z + b4.z;
    float o3 = (v.w - mu) * rstd * g.w + b4.w;
    __half2 ha = __floats2half2_rn(o0, o1);
    __half2 hb = __floats2half2_rn(o2, o3);
    size_t base = (size_t)row * DIM + t * 4;
    *reinterpret_cast<__half2*>(&out_hi[base])     = ha;
    *reinterpret_cast<__half2*>(&out_hi[base + 2]) = hb;
}

// ============================ weight/bias prep (fused, q-scale folded) ============================
__global__ void __launch_bounds__(256) prep_kernel(
    const float* __restrict__ wq, const float* __restrict__ wo,
    const float* __restrict__ bq,
    __half* __restrict__ wq_h, __half* __restrict__ wo_h,
    float* __restrict__ bq_s)
{
    const int n1 = DIM * QKV_N;
    const int n2 = DIM * DIM;
    int stride = gridDim.x * blockDim.x;
    for (int idx = blockIdx.x * blockDim.x + threadIdx.x;
         idx < n1 + n2 + QKV_N; idx += stride) {
        if (idx < n1) {
            int col = idx % QKV_N;
            float sc = ((col % 192) < 64) ? Q_SCALE : 1.0f;
            wq_h[idx] = __float2half_rn(wq[idx] * sc);
        } else if (idx < n1 + n2) {
            wo_h[idx - n1] = __float2half_rn(wo[idx - n1]);
        } else {
            int col = idx - n1 - n2;
            float sc = ((col % 192) < 64) ? Q_SCALE : 1.0f;
            bq_s[col] = bq[col] * sc;
        }
    }
}

// ============================ fp16 single-pass MMA GEMM 128x128, 32-K slices, 3-stage ============================
// Warp tile 32x64 (4x2 layout), 256 threads, 2 CTA/SM.
// MODE 0: QKV — scatter fp16 into q/k/v ([b,h,s,d]); scales pre-folded.
// MODE 1: fp32 C.
#define GA_STRIDE 40                        // halves per A row (32 data + 8 pad)
#define GB_STRIDE 136                       // halves per B row (128 data + 8 pad)
#define GA_BYTES  (128 * GA_STRIDE * 2)     // 10240
#define GB_BYTES  (32 * GB_STRIDE * 2)      // 8704
#define GSTAGE    (GA_BYTES + GB_BYTES)     // 18944
#define G_OFF_B   GA_BYTES
template <int MODE>
__global__ void __launch_bounds__(256, 2) mma_gemm(
    const __half* __restrict__ Ag,
    const __half* __restrict__ Bg,
    const float* __restrict__ bias,
    float* __restrict__ Cout,
    int M, int N, int K,
    __half* __restrict__ qh, __half* __restrict__ kh, __half* __restrict__ vh)
{
    extern __shared__ __align__(16) char smem[];
    uint32_t smem_base = s2u(smem);

    int tid = threadIdx.x;
    int lane = tid & 31;
    int wid = tid >> 5;
    int wm = wid & 3;
    int wn = wid >> 2;
    int m0 = blockIdx.y * 128;
    int n0 = blockIdx.x * 128;

    int arow = tid >> 1;
    int acol = (tid & 1) * 16;
    int brow = tid >> 3;
    int bcol = (tid & 7) * 16;

    const __half* pA = Ag + (size_t)(m0 + arow) * K + acol;
    const __half* pB = Bg + (size_t)brow * N + n0 + bcol;
    uint32_t aoff = (arow * GA_STRIDE + acol) * 2;
    uint32_t boff = (brow * GB_STRIDE + bcol) * 2;

    float acc[2][8][4];
    #pragma unroll
    for (int i = 0; i < 2; i++)
        #pragma unroll
        for (int j = 0; j < 8; j++)
            #pragma unroll
            for (int e = 0; e < 4; e++) acc[i][j][e] = 0.f;

    int niter = K / 32;

    auto issue = [&](int kt, int s) {
        uint32_t st = smem_base + s * GSTAGE;
        int ko = kt * 32;
        const __half* a = pA + ko;
        const __half* b = pB + (size_t)ko * N;
        cp16(st + aoff,              a);
        cp16(st + aoff + 16,         a + 8);
        cp16(st + G_OFF_B + boff,      b);
        cp16(st + G_OFF_B + boff + 16, b + 8);
        cp_commit();
    };

    issue(0, 0);
    issue(1, 1);

    int lrow = lane & 15;
    int lcol = (lane >> 4) * 8;
    uint32_t baseA[2];
    #pragma unroll
    for (int i = 0; i < 2; i++)
        baseA[i] = smem_base + ((wm * 32 + i * 16 + lrow) * GA_STRIDE + lcol) * 2;
    uint32_t baseB[4];
    #pragma unroll
    for (int jj = 0; jj < 4; jj++)
        baseB[jj] = smem_base + G_OFF_B + (lrow * GB_STRIDE + wn * 64 + jj * 16 + lcol) * 2;

    int s = 0;
    for (int kt = 0; kt < niter; kt++) {
        if (kt + 1 < niter) cp_wait<1>();
        else                cp_wait<0>();
        __syncthreads();

        if (kt + 2 < niter) {
            int s2 = s + 2; if (s2 >= 3) s2 -= 3;
            issue(kt + 2, s2);
        }

        uint32_t offS = (uint32_t)(s * GSTAGE);
        #pragma unroll
        for (int ss = 0; ss < 2; ss++) {
            uint32_t aSub = offS + ss * 32;
            uint32_t bSub = offS + ss * 16 * GB_STRIDE * 2;

            uint32_t ah[2][4], bb[8][2];
            #pragma unroll
            for (int i = 0; i < 2; i++)
                ldsm4(ah[i], baseA[i] + aSub);
            #pragma unroll
            for (int jj = 0; jj < 4; jj++) {
                uint32_t r[4];
                ldsm4t(r, baseB[jj] + bSub);
                bb[jj * 2][0] = r[0]; bb[jj * 2][1] = r[1];
                bb[jj * 2 + 1][0] = r[2]; bb[jj * 2 + 1][1] = r[3];
            }
            #pragma unroll
            for (int i = 0; i < 2; i++)
                #pragma unroll
                for (int j = 0; j < 8; j++)
                    mma_f16(acc[i][j], ah[i], bb[j]);
        }
        s++; if (s == 3) s = 0;
    }

    int gid = lane >> 2, tig = lane & 3;
    #pragma unroll
    for (int i = 0; i < 2; i++) {
        #pragma unroll
        for (int j = 0; j < 8; j++) {
            int n = n0 + wn * 64 + j * 8 + 2 * tig;
            if (MODE == 0) {
                int hq = n / 192;
                int f = n - hq * 192;
                __half* dst;
                int off;
                if (f < 64)       { dst = qh; off = f; }
                else if (f < 128) { dst = kh; off = f - 64; }
                else              { dst = vh; off = f - 128; }
                float b0 = bias[n], b1 = bias[n + 1];
                #pragma unroll
                for (int rh = 0; rh < 2; rh++) {
                    int m = m0 + wm * 32 + i * 16 + gid + rh * 8;
                    float v0 = acc[i][j][rh * 2 + 0] + b0;
                    float v1 = acc[i][j][rh * 2 + 1] + b1;
                    int bb2 = m >> 11;
                    int ss2 = m & 2047;
                    size_t base = (((size_t)(bb2 * HEADS + hq)) * SEQ + ss2) * HD;
                    __half2 h2 = __floats2half2_rn(v0, v1);
                    *reinterpret_cast<uint32_t*>(&dst[base + off]) =
                        *reinterpret_cast<uint32_t*>(&h2);
                }
            } else {
                float b0 = bias[n], b1 = bias[n + 1];
                #pragma unroll
                for (int rh = 0; rh < 2; rh++) {
                    int m = m0 + wm * 32 + i * 16 + gid + rh * 8;
                    float v0 = acc[i][j][rh * 2 + 0] + b0;
                    float v1 = acc[i][j][rh * 2 + 1] + b1;
                    *reinterpret_cast<float2*>(&Cout[(size_t)m * N + n]) = make_float2(v0, v1);
                }
            }
        }
    }
}

// ============================ Tensor-core flash attention ============================
// 64-key stages (round-14 proven shape), log2-domain MUFU softmax,
// deferred l-sum reduction (epilogue-only shuffle).
#define KVSTRIDE (64 * 72)
__global__ void __launch_bounds__(256) attn_mma_kernel(
    const __half* __restrict__ qh_g,
    const __half* __restrict__ kh_g,
    const __half* __restrict__ vh_g,
    __half* __restrict__ y_hi)
{
    extern __shared__ __half smb[];
    __half* sQh = smb;                      // [128][72]
    __half* sKh = sQh + 128 * 72;           // [2][64][72]
    __half* sVh = sKh + 2 * KVSTRIDE;       // [2][64][72]

    int bh = blockIdx.x;
    int qt = (gridDim.y - 1) - blockIdx.y;   // heavy tiles first
    int tid = threadIdx.x;
    int lane = tid & 31;
    int w = tid >> 5;
    int gid = lane >> 2, tig = lane & 3;
    int lrow = lane & 15, lcol = (lane >> 4) * 8;

    int q0 = qt * 128;
    const size_t bhoff = (size_t)bh * SEQ * HD;

    int kvr = tid >> 3;
    int kvd = (tid & 7) * 8;
    auto issue_kv = [&](int kt, int st) {
        int c0 = kt * 64;
        size_t base = st * KVSTRIDE;
        #pragma unroll
        for (int i = 0; i < 2; i++) {
            int r = kvr + i * 32;
            size_t g = bhoff + (size_t)(c0 + r) * HD + kvd;
            size_t sm = base + r * 72 + kvd;
            cp16(s2u(&sKh[sm]), &kh_g[g]);
            cp16(s2u(&sVh[sm]), &vh_g[g]);
        }
        cp_commit();
    };

    int ktmax = 2 * qt + 1;
    issue_kv(0, 0);

    #pragma unroll
    for (int i = 0; i < 4; i++) {
        int chunk = tid + i * 256;
        int r = chunk >> 3, d8 = (chunk & 7) * 8;
        size_t g = bhoff + (size_t)(q0 + r) * HD + d8;
        *reinterpret_cast<uint4*>(&sQh[r * 72 + d8]) = *reinterpret_cast<const uint4*>(&qh_g[g]);
    }
    __syncthreads();

    uint32_t qfh[4][4];
    #pragma unroll
    for (int kk = 0; kk < 4; kk++)
        ldsm4(qfh[kk], s2u(&sQh[(w * 16 + lrow) * 72 + kk * 16 + lcol]));

    float m_r[2] = {-1e30f, -1e30f};
    float l_r[2] = {0.f, 0.f};          // per-thread PARTIAL sums (reduced in epilogue)
    float o[8][4];
    #pragma unroll
    for (int j = 0; j < 8; j++)
        #pragma unroll
        for (int c = 0; c < 4; c++) o[j][c] = 0.f;

    for (int kt = 0; kt <= ktmax; kt++) {
        int c0 = kt * 64;
        int st = kt & 1;
        uint32_t offKV = (uint32_t)(st * KVSTRIDE * 2);

        cp_wait<0>();
        __syncthreads();

        if (kt < ktmax) issue_kv(kt + 1, (kt + 1) & 1);

        float s[8][4];
        #pragma unroll
        for (int j = 0; j < 8; j++)
            #pragma unroll
            for (int c = 0; c < 4; c++) s[j][c] = 0.f;

        #pragma unroll
        for (int kk = 0; kk < 4; kk++) {
            #pragma unroll
            for (int g2 = 0; g2 < 4; g2++) {
                uint32_t rh[4];
                ldsm4(rh, s2u(&sKh[(g2 * 16 + lrow) * 72 + kk * 16 + lcol]) + offKV);
                uint32_t b0h[2] = {rh[0], rh[2]}, b1h[2] = {rh[1], rh[3]};
                mma_f16(s[g2 * 2],     qfh[kk], b0h);
                mma_f16(s[g2 * 2 + 1], qfh[kk], b1h);
            }
        }

        if (kt >= 2 * qt) {
            int row0 = q0 + w * 16 + gid;
            #pragma unroll
            for (int j = 0; j < 8; j++) {
                int col = c0 + j * 8 + 2 * tig;
                if (col     > row0)     s[j][0] = -1e30f;
                if (col + 1 > row0)     s[j][1] = -1e30f;
                if (col     > row0 + 8) s[j][2] = -1e30f;
                if (col + 1 > row0 + 8) s[j][3] = -1e30f;
            }
        }

        // ---- online softmax (log2 domain, deferred l reduction) ----
        float mx0 = -1e30f, mx1 = -1e30f;
        #pragma unroll
        for (int j = 0; j < 8; j++) {
            mx0 = fmaxf(mx0, fmaxf(s[j][0], s[j][1]));
            mx1 = fmaxf(mx1, fmaxf(s[j][2], s[j][3]));
        }
        mx0 = fmaxf(mx0, __shfl_xor_sync(0xffffffffu, mx0, 1));
        mx0 = fmaxf(mx0, __shfl_xor_sync(0xffffffffu, mx0, 2));
        mx1 = fmaxf(mx1, __shfl_xor_sync(0xffffffffu, mx1, 1));
        mx1 = fmaxf(mx1, __shfl_xor_sync(0xffffffffu, mx1, 2));
        float mn0 = fmaxf(m_r[0], mx0);
        float mn1 = fmaxf(m_r[1], mx1);
        float corr0 = ex2(m_r[0] - mn0);
        float corr1 = ex2(m_r[1] - mn1);
        float rs0 = 0.f, rs1 = 0.f;
        #pragma unroll
        for (int j = 0; j < 8; j++) {
            s[j][0] = ex2(s[j][0] - mn0); rs0 += s[j][0];
            s[j][1] = ex2(s[j][1] - mn0); rs0 += s[j][1];
            s[j][2] = ex2(s[j][2] - mn1); rs1 += s[j][2];
            s[j][3] = ex2(s[j][3] - mn1); rs1 += s[j][3];
        }
        l_r[0] = l_r[0] * corr0 + rs0;   // partial (own columns only)
        l_r[1] = l_r[1] * corr1 + rs1;
        m_r[0] = mn0; m_r[1] = mn1;
        #pragma unroll
        for (int j = 0; j < 8; j++) {
            o[j][0] *= corr0; o[j][1] *= corr0;
            o[j][2] *= corr1; o[j][3] *= corr1;
        }

        // ---- O += P V (P fp16) ----
        #pragma unroll
        for (int kk = 0; kk < 4; kk++) {
            uint32_t ph[4];
            __half2 p0 = __floats2half2_rn(s[2 * kk][0],     s[2 * kk][1]);
            __half2 p1 = __floats2half2_rn(s[2 * kk][2],     s[2 * kk][3]);
            __half2 p2 = __floats2half2_rn(s[2 * kk + 1][0], s[2 * kk + 1][1]);
            __half2 p3 = __floats2half2_rn(s[2 * kk + 1][2], s[2 * kk + 1][3]);
            ph[0] = *reinterpret_cast<uint32_t*>(&p0);
            ph[1] = *reinterpret_cast<uint32_t*>(&p1);
            ph[2] = *reinterpret_cast<uint32_t*>(&p2);
            ph[3] = *reinterpret_cast<uint32_t*>(&p3);
            #pragma unroll
            for (int g2 = 0; g2 < 4; g2++) {
                uint32_t rvh[4];
                ldsm4t(rvh, s2u(&sVh[(kk * 16 + lrow) * 72 + g2 * 16 + lcol]) + offKV);
                uint32_t bh0[2] = {rvh[0], rvh[1]}, bh1[2] = {rvh[2], rvh[3]};
                mma_f16(o[g2 * 2],     ph, bh0);
                mma_f16(o[g2 * 2 + 1], ph, bh1);
            }
        }
    }

    // epilogue: reduce deferred l across the 4 threads of each row, then write
    float l0 = l_r[0], l1 = l_r[1];
    l0 += __shfl_xor_sync(0xffffffffu, l0, 1);
    l0 += __shfl_xor_sync(0xffffffffu, l0, 2);
    l1 += __shfl_xor_sync(0xffffffffu, l1, 1);
    l1 += __shfl_xor_sync(0xffffffffu, l1, 2);

    int b = bh >> 4, hh = bh & 15;
    float inv0 = 1.0f / l0;
    float inv1 = 1.0f / l1;
    #pragma unroll
    for (int h2 = 0; h2 < 2; h2++) {
        int srow = q0 + w * 16 + gid + h2 * 8;
        float inv = h2 ? inv1 : inv0;
        size_t base = (((size_t)(b * SEQ + srow)) * HEADS + hh) * HD;
        #pragma unroll
        for (int j = 0; j < 8; j++) {
            float a = o[j][h2 * 2 + 0] * inv;
            float c = o[j][h2 * 2 + 1] * inv;
            __half2 h2v = __floats2half2_rn(a, c);
            int d = j * 8 + 2 * tig;
            *reinterpret_cast<uint32_t*>(&y_hi[base + d]) = *reinterpret_cast<uint32_t*>(&h2v);
        }
    }
}

// ============================ launch ============================
extern "C" void kernel_launch(void* const* d_in, const int* in_sizes, int n_in,
                              void* d_out, int out_size)
{
    const float* x        = (const float*)d_in[0];
    const float* ln_scale = (const float*)d_in[2];
    const float* ln_bias  = (const float*)d_in[3];
    const float* w_qkv    = (const float*)d_in[4];
    const float* b_qkv    = (const float*)d_in[5];
    const float* w_out    = (const float*)d_in[6];
    const float* b_out    = (const float*)d_in[7];
    float* out = (float*)d_out;

    __half *xn_hi, *wq_hi, *wo_hi, *y_hi;
    __half *qh, *kh, *vh;
    float* bq_s;
    cudaGetSymbolAddress((void**)&xn_hi, g_xn_hi);
    cudaGetSymbolAddress((void**)&wq_hi, g_wq_hi);
    cudaGetSymbolAddress((void**)&wo_hi, g_wo_hi);
    cudaGetSymbolAddress((void**)&y_hi,  g_y_hi);
    cudaGetSymbolAddress((void**)&qh, g_qh);
    cudaGetSymbolAddress((void**)&kh, g_kh);
    cudaGetSymbolAddress((void**)&vh, g_vh);
    cudaGetSymbolAddress((void**)&bq_s, g_bq_s);

    // 1. LayerNorm -> fp16
    ln_kernel<<<ROWS, 256>>>(x, ln_scale, ln_bias, xn_hi);

    // 1b. fused weight/bias prep (q-scale folded)
    prep_kernel<<<768, 256>>>(w_qkv, w_out, b_qkv, wq_hi, wo_hi, bq_s);

    int gemm_smem = 3 * GSTAGE;   // 56832

    // 2. QKV projection -> q/k/v fp16 [b,h,s,d]
    {
        cudaFuncSetAttribute(mma_gemm<0>,
                             cudaFuncAttributeMaxDynamicSharedMemorySize, gemm_smem);
        dim3 grid(QKV_N / 128, ROWS / 128);  // (24, 64)
        mma_gemm<0><<<grid, 256, gemm_smem>>>(xn_hi, wq_hi, bq_s, nullptr,
                                              ROWS, QKV_N, DIM, qh, kh, vh);
    }

    // 3. tensor-core causal flash attention (64-key stages, deferred l)
    {
        int smem = (128 * 72 + 4 * KVSTRIDE) * sizeof(__half);  // 55296
        cudaFuncSetAttribute(attn_mma_kernel,
                             cudaFuncAttributeMaxDynamicSharedMemorySize, smem);
        dim3 grid(BATCH * HEADS, SEQ / 128);  // (64, 16)
        attn_mma_kernel<<<grid, 256, smem>>>(qh, kh, vh, y_hi);
    }

    // 4. output projection -> d_out
    {
        cudaFuncSetAttribute(mma_gemm<1>,
                             cudaFuncAttributeMaxDynamicSharedMemorySize, gemm_smem);
        dim3 grid(DIM / 128, ROWS / 128);    // (8, 64)
        mma_gemm<1><<<grid, 256, gemm_smem>>>(y_hi, wo_hi, b_out, out,
                                              ROWS, DIM, DIM,
                                              nullptr, nullptr, nullptr);
    }
}

// round 17
// speedup vs baseline: 1.0574x; 1.0157x over previous
#include <cuda_runtime.h>
#include <cuda_fp16.h>
#include <cstdint>

// Problem constants
#define BATCH 4
#define SEQ   2048
#define DIM   1024
#define HEADS 16
#define HD    64
#define ROWS  (BATCH * SEQ)          // 8192
#define QKV_N (HEADS * 3 * HD)       // 3072
#define BHSD  (BATCH * HEADS * SEQ * HD)
#define Q_SCALE (0.125f * 1.4426950408889634f)

// -------- scratch (static device globals; no allocation allowed) --------
__device__ __half g_xn_hi[ROWS * DIM];
__device__ __half g_wq_hi[DIM * QKV_N];   // q-columns pre-scaled by Q_SCALE
__device__ __half g_wo_hi[DIM * DIM];
__device__ float  g_bq_s[QKV_N];          // bias, q part pre-scaled
__device__ __half g_qh[BHSD];   // [b,h,s,d] fp16 (pre-scaled via weights)
__device__ __half g_kh[BHSD];
__device__ __half g_vh[BHSD];
__device__ __half g_y_hi[ROWS * DIM];   // attn out [b,s,h,d]

// ============================ helpers ============================
__device__ __forceinline__ uint32_t s2u(const void* p) {
    return (uint32_t)__cvta_generic_to_shared(p);
}
__device__ __forceinline__ void ldsm4(uint32_t* r, uint32_t addr) {
    asm volatile("ldmatrix.sync.aligned.m8n8.x4.shared.b16 {%0,%1,%2,%3}, [%4];\n"
                 : "=r"(r[0]), "=r"(r[1]), "=r"(r[2]), "=r"(r[3]) : "r"(addr));
}
__device__ __forceinline__ void ldsm4t(uint32_t* r, uint32_t addr) {
    asm volatile("ldmatrix.sync.aligned.m8n8.x4.trans.shared.b16 {%0,%1,%2,%3}, [%4];\n"
                 : "=r"(r[0]), "=r"(r[1]), "=r"(r[2]), "=r"(r[3]) : "r"(addr));
}
__device__ __forceinline__ void mma_f16(float* c, const uint32_t* a, const uint32_t* b) {
    asm volatile(
        "mma.sync.aligned.m16n8k16.row.col.f32.f16.f16.f32 "
        "{%0,%1,%2,%3}, {%4,%5,%6,%7}, {%8,%9}, {%0,%1,%2,%3};\n"
        : "+f"(c[0]), "+f"(c[1]), "+f"(c[2]), "+f"(c[3])
        : "r"(a[0]), "r"(a[1]), "r"(a[2]), "r"(a[3]), "r"(b[0]), "r"(b[1]));
}
__device__ __forceinline__ void cp16(uint32_t smem_dst, const void* gmem_src) {
    asm volatile("cp.async.cg.shared.global [%0], [%1], 16;\n"
                 :: "r"(smem_dst), "l"(gmem_src));
}
__device__ __forceinline__ void cp_commit() {
    asm volatile("cp.async.commit_group;\n");
}
template <int N>
__device__ __forceinline__ void cp_wait() {
    asm volatile("cp.async.wait_group %0;\n" :: "n"(N));
}
__device__ __forceinline__ float ex2(float x) {
    float r;
    asm("ex2.approx.f32 %0, %1;" : "=f"(r) : "f"(x));
    return r;
}

// ============================ LayerNorm -> fp16 ============================
__global__ void __launch_bounds__(256) ln_kernel(
    const float* __restrict__ x,
    const float* __restrict__ gamma,
    const float* __restrict__ beta,
    __half* __restrict__ out_hi)
{
    int row = blockIdx.x;
    int t = threadIdx.x;
    const float4* xr = reinterpret_cast<const float4*>(x + (size_t)row * DIM);
    float4 v = xr[t];
    float s1 = v.x + v.y + v.z + v.w;
    float s2 = v.x*v.x + v.y*v.y + v.z*v.z + v.w*v.w;
    #pragma unroll
    for (int o = 16; o > 0; o >>= 1) {
        s1 += __shfl_xor_sync(0xffffffffu, s1, o);
        s2 += __shfl_xor_sync(0xffffffffu, s2, o);
    }
    __shared__ float r1[8], r2[8];
    __shared__ float sh_mu, sh_rstd;
    if ((t & 31) == 0) { r1[t >> 5] = s1; r2[t >> 5] = s2; }
    __syncthreads();
    if (t == 0) {
        float a = 0.f, b = 0.f;
        #pragma unroll
        for (int i = 0; i < 8; i++) { a += r1[i]; b += r2[i]; }
        float mu  = a * (1.0f / DIM);
        float var = b * (1.0f / DIM) - mu * mu;
        sh_mu = mu;
        sh_rstd = rsqrtf(var + 1e-6f);
    }
    __syncthreads();
    float mu = sh_mu, rstd = sh_rstd;
    float4 g = reinterpret_cast<const float4*>(gamma)[t];
    float4 b4 = reinterpret_cast<const float4*>(beta)[t];
    float o0 = (v.x - mu) * rstd * g.x + b4.x;
    float o1 = (v.y - mu) * rstd * g.y + b4.y;
    float o2 = (v.z - mu) * rstd * g.z + b4.z;
    float o3 = (v.w - mu) * rstd * g.w + b4.w;
    __half2 ha = __floats2half2_rn(o0, o1);
    __half2 hb = __floats2half2_rn(o2, o3);
    size_t base = (size_t)row * DIM + t * 4;
    *reinterpret_cast<__half2*>(&out_hi[base])     = ha;
    *reinterpret_cast<__half2*>(&out_hi[base + 2]) = hb;
}

// ============================ weight/bias prep (fused, q-scale folded) ============================
__global__ void __launch_bounds__(256) prep_kernel(
    const float* __restrict__ wq, const float* __restrict__ wo,
    const float* __restrict__ bq,
    __half* __restrict__ wq_h, __half* __restrict__ wo_h,
    float* __restrict__ bq_s)
{
    const int n1 = DIM * QKV_N;
    const int n2 = DIM * DIM;
    int stride = gridDim.x * blockDim.x;
    for (int idx = blockIdx.x * blockDim.x + threadIdx.x;
         idx < n1 + n2 + QKV_N; idx += stride) {
        if (idx < n1) {
            int col = idx % QKV_N;
            float sc = ((col % 192) < 64) ? Q_SCALE : 1.0f;
            wq_h[idx] = __float2half_rn(wq[idx] * sc);
        } else if (idx < n1 + n2) {
            wo_h[idx - n1] = __float2half_rn(wo[idx - n1]);
        } else {
            int col = idx - n1 - n2;
            float sc = ((col % 192) < 64) ? Q_SCALE : 1.0f;
            bq_s[col] = bq[col] * sc;
        }
    }
}

// ============================ fp16 single-pass MMA GEMM 128x128, 32-K slices, 3-stage ============================
// Warp tile 32x64 (4x2 layout), 256 threads, 2 CTA/SM.
// MODE 0: QKV — scatter fp16 into q/k/v ([b,h,s,d]); scales pre-folded.
// MODE 1: fp32 C.
#define GA_STRIDE 40                        // halves per A row (32 data + 8 pad)
#define GB_STRIDE 136                       // halves per B row (128 data + 8 pad)
#define GA_BYTES  (128 * GA_STRIDE * 2)     // 10240
#define GB_BYTES  (32 * GB_STRIDE * 2)      // 8704
#define GSTAGE    (GA_BYTES + GB_BYTES)     // 18944
#define G_OFF_B   GA_BYTES
template <int MODE>
__global__ void __launch_bounds__(256, 2) mma_gemm(
    const __half* __restrict__ Ag,
    const __half* __restrict__ Bg,
    const float* __restrict__ bias,
    float* __restrict__ Cout,
    int M, int N, int K,
    __half* __restrict__ qh, __half* __restrict__ kh, __half* __restrict__ vh)
{
    extern __shared__ __align__(16) char smem[];
    uint32_t smem_base = s2u(smem);

    int tid = threadIdx.x;
    int lane = tid & 31;
    int wid = tid >> 5;
    int wm = wid & 3;
    int wn = wid >> 2;
    int m0 = blockIdx.y * 128;
    int n0 = blockIdx.x * 128;

    int arow = tid >> 1;
    int acol = (tid & 1) * 16;
    int brow = tid >> 3;
    int bcol = (tid & 7) * 16;

    const __half* pA = Ag + (size_t)(m0 + arow) * K + acol;
    const __half* pB = Bg + (size_t)brow * N + n0 + bcol;
    uint32_t aoff = (arow * GA_STRIDE + acol) * 2;
    uint32_t boff = (brow * GB_STRIDE + bcol) * 2;

    float acc[2][8][4];
    #pragma unroll
    for (int i = 0; i < 2; i++)
        #pragma unroll
        for (int j = 0; j < 8; j++)
            #pragma unroll
            for (int e = 0; e < 4; e++) acc[i][j][e] = 0.f;

    int niter = K / 32;

    auto issue = [&](int kt, int s) {
        uint32_t st = smem_base + s * GSTAGE;
        int ko = kt * 32;
        const __half* a = pA + ko;
        const __half* b = pB + (size_t)ko * N;
        cp16(st + aoff,              a);
        cp16(st + aoff + 16,         a + 8);
        cp16(st + G_OFF_B + boff,      b);
        cp16(st + G_OFF_B + boff + 16, b + 8);
        cp_commit();
    };

    issue(0, 0);
    issue(1, 1);

    int lrow = lane & 15;
    int lcol = (lane >> 4) * 8;
    uint32_t baseA[2];
    #pragma unroll
    for (int i = 0; i < 2; i++)
        baseA[i] = smem_base + ((wm * 32 + i * 16 + lrow) * GA_STRIDE + lcol) * 2;
    uint32_t baseB[4];
    #pragma unroll
    for (int jj = 0; jj < 4; jj++)
        baseB[jj] = smem_base + G_OFF_B + (lrow * GB_STRIDE + wn * 64 + jj * 16 + lcol) * 2;

    int s = 0;
    for (int kt = 0; kt < niter; kt++) {
        if (kt + 1 < niter) cp_wait<1>();
        else                cp_wait<0>();
        __syncthreads();

        if (kt + 2 < niter) {
            int s2 = s + 2; if (s2 >= 3) s2 -= 3;
            issue(kt + 2, s2);
        }

        uint32_t offS = (uint32_t)(s * GSTAGE);
        #pragma unroll
        for (int ss = 0; ss < 2; ss++) {
            uint32_t aSub = offS + ss * 32;
            uint32_t bSub = offS + ss * 16 * GB_STRIDE * 2;

            uint32_t ah[2][4], bb[8][2];
            #pragma unroll
            for (int i = 0; i < 2; i++)
                ldsm4(ah[i], baseA[i] + aSub);
            #pragma unroll
            for (int jj = 0; jj < 4; jj++) {
                uint32_t r[4];
                ldsm4t(r, baseB[jj] + bSub);
                bb[jj * 2][0] = r[0]; bb[jj * 2][1] = r[1];
                bb[jj * 2 + 1][0] = r[2]; bb[jj * 2 + 1][1] = r[3];
            }
            #pragma unroll
            for (int i = 0; i < 2; i++)
                #pragma unroll
                for (int j = 0; j < 8; j++)
                    mma_f16(acc[i][j], ah[i], bb[j]);
        }
        s++; if (s == 3) s = 0;
    }

    int gid = lane >> 2, tig = lane & 3;
    #pragma unroll
    for (int i = 0; i < 2; i++) {
        #pragma unroll
        for (int j = 0; j < 8; j++) {
            int n = n0 + wn * 64 + j * 8 + 2 * tig;
            if (MODE == 0) {
                int hq = n / 192;
                int f = n - hq * 192;
                __half* dst;
                int off;
                if (f < 64)       { dst = qh; off = f; }
                else if (f < 128) { dst = kh; off = f - 64; }
                else              { dst = vh; off = f - 128; }
                float b0 = bias[n], b1 = bias[n + 1];
                #pragma unroll
                for (int rh = 0; rh < 2; rh++) {
                    int m = m0 + wm * 32 + i * 16 + gid + rh * 8;
                    float v0 = acc[i][j][rh * 2 + 0] + b0;
                    float v1 = acc[i][j][rh * 2 + 1] + b1;
                    int bb2 = m >> 11;
                    int ss2 = m & 2047;
                    size_t base = (((size_t)(bb2 * HEADS + hq)) * SEQ + ss2) * HD;
                    __half2 h2 = __floats2half2_rn(v0, v1);
                    *reinterpret_cast<uint32_t*>(&dst[base + off]) =
                        *reinterpret_cast<uint32_t*>(&h2);
                }
            } else {
                float b0 = bias[n], b1 = bias[n + 1];
                #pragma unroll
                for (int rh = 0; rh < 2; rh++) {
                    int m = m0 + wm * 32 + i * 16 + gid + rh * 8;
                    float v0 = acc[i][j][rh * 2 + 0] + b0;
                    float v1 = acc[i][j][rh * 2 + 1] + b1;
                    *reinterpret_cast<float2*>(&Cout[(size_t)m * N + n]) = make_float2(v0, v1);
                }
            }
        }
    }
}

// ============================ Tensor-core flash attention ============================
// 64 query rows / 4 warps / 128 threads -> 4 CTAs/SM (4 independent barrier domains).
// 64-key 2-stage KV pipeline, log2-domain MUFU softmax, deferred l reduction.
#define KVSTRIDE (64 * 72)
__global__ void __launch_bounds__(128, 4) attn_mma_kernel(
    const __half* __restrict__ qh_g,
    const __half* __restrict__ kh_g,
    const __half* __restrict__ vh_g,
    __half* __restrict__ y_hi)
{
    extern __shared__ __half smb[];
    __half* sQh = smb;                      // [64][72]
    __half* sKh = sQh + 64 * 72;            // [2][64][72]
    __half* sVh = sKh + 2 * KVSTRIDE;       // [2][64][72]

    int bh = blockIdx.x;
    int qt = (gridDim.y - 1) - blockIdx.y;   // heavy tiles first
    int tid = threadIdx.x;
    int lane = tid & 31;
    int w = tid >> 5;                        // 0..3
    int gid = lane >> 2, tig = lane & 3;
    int lrow = lane & 15, lcol = (lane >> 4) * 8;

    int q0 = qt * 64;
    const size_t bhoff = (size_t)bh * SEQ * HD;

    int kvr = tid >> 3;                 // 0..15, 4 blocks of +16
    int kvd = (tid & 7) * 8;
    auto issue_kv = [&](int kt, int st) {
        int c0 = kt * 64;
        size_t base = st * KVSTRIDE;
        #pragma unroll
        for (int i = 0; i < 4; i++) {
            int r = kvr + i * 16;
            size_t g = bhoff + (size_t)(c0 + r) * HD + kvd;
            size_t sm = base + r * 72 + kvd;
            cp16(s2u(&sKh[sm]), &kh_g[g]);
            cp16(s2u(&sVh[sm]), &vh_g[g]);
        }
        cp_commit();
    };

    int ktmax = qt;                     // keys 0 .. q0+63 -> tiles 0..qt
    issue_kv(0, 0);

    // load Q tile (64 x 64)
    #pragma unroll
    for (int i = 0; i < 4; i++) {
        int chunk = tid + i * 128;       // 0..511
        int r = chunk >> 3, d8 = (chunk & 7) * 8;
        size_t g = bhoff + (size_t)(q0 + r) * HD + d8;
        *reinterpret_cast<uint4*>(&sQh[r * 72 + d8]) = *reinterpret_cast<const uint4*>(&qh_g[g]);
    }
    __syncthreads();

    uint32_t qfh[4][4];
    #pragma unroll
    for (int kk = 0; kk < 4; kk++)
        ldsm4(qfh[kk], s2u(&sQh[(w * 16 + lrow) * 72 + kk * 16 + lcol]));

    float m_r[2] = {-1e30f, -1e30f};
    float l_r[2] = {0.f, 0.f};          // per-thread partial sums (reduced in epilogue)
    float o[8][4];
    #pragma unroll
    for (int j = 0; j < 8; j++)
        #pragma unroll
        for (int c = 0; c < 4; c++) o[j][c] = 0.f;

    for (int kt = 0; kt <= ktmax; kt++) {
        int c0 = kt * 64;
        int st = kt & 1;
        uint32_t offKV = (uint32_t)(st * KVSTRIDE * 2);

        cp_wait<0>();
        __syncthreads();   // stage st ready; all warps done reading other stage

        if (kt < ktmax) issue_kv(kt + 1, (kt + 1) & 1);

        float s[8][4];
        #pragma unroll
        for (int j = 0; j < 8; j++)
            #pragma unroll
            for (int c = 0; c < 4; c++) s[j][c] = 0.f;

        #pragma unroll
        for (int kk = 0; kk < 4; kk++) {
            #pragma unroll
            for (int g2 = 0; g2 < 4; g2++) {
                uint32_t rh[4];
                ldsm4(rh, s2u(&sKh[(g2 * 16 + lrow) * 72 + kk * 16 + lcol]) + offKV);
                uint32_t b0h[2] = {rh[0], rh[2]}, b1h[2] = {rh[1], rh[3]};
                mma_f16(s[g2 * 2],     qfh[kk], b0h);
                mma_f16(s[g2 * 2 + 1], qfh[kk], b1h);
            }
        }

        if (kt == ktmax) {   // single diagonal tile
            int row0 = q0 + w * 16 + gid;
            #pragma unroll
            for (int j = 0; j < 8; j++) {
                int col = c0 + j * 8 + 2 * tig;
                if (col     > row0)     s[j][0] = -1e30f;
                if (col + 1 > row0)     s[j][1] = -1e30f;
                if (col     > row0 + 8) s[j][2] = -1e30f;
                if (col + 1 > row0 + 8) s[j][3] = -1e30f;
            }
        }

        // ---- online softmax (log2 domain, deferred l reduction) ----
        float mx0 = -1e30f, mx1 = -1e30f;
        #pragma unroll
        for (int j = 0; j < 8; j++) {
            mx0 = fmaxf(mx0, fmaxf(s[j][0], s[j][1]));
            mx1 = fmaxf(mx1, fmaxf(s[j][2], s[j][3]));
        }
        mx0 = fmaxf(mx0, __shfl_xor_sync(0xffffffffu, mx0, 1));
        mx0 = fmaxf(mx0, __shfl_xor_sync(0xffffffffu, mx0, 2));
        mx1 = fmaxf(mx1, __shfl_xor_sync(0xffffffffu, mx1, 1));
        mx1 = fmaxf(mx1, __shfl_xor_sync(0xffffffffu, mx1, 2));
        float mn0 = fmaxf(m_r[0], mx0);
        float mn1 = fmaxf(m_r[1], mx1);
        float corr0 = ex2(m_r[0] - mn0);
        float corr1 = ex2(m_r[1] - mn1);
        float rs0 = 0.f, rs1 = 0.f;
        #pragma unroll
        for (int j = 0; j < 8; j++) {
            s[j][0] = ex2(s[j][0] - mn0); rs0 += s[j][0];
            s[j][1] = ex2(s[j][1] - mn0); rs0 += s[j][1];
            s[j][2] = ex2(s[j][2] - mn1); rs1 += s[j][2];
            s[j][3] = ex2(s[j][3] - mn1); rs1 += s[j][3];
        }
        l_r[0] = l_r[0] * corr0 + rs0;
        l_r[1] = l_r[1] * corr1 + rs1;
        m_r[0] = mn0; m_r[1] = mn1;
        #pragma unroll
        for (int j = 0; j < 8; j++) {
            o[j][0] *= corr0; o[j][1] *= corr0;
            o[j][2] *= corr1; o[j][3] *= corr1;
        }

        // ---- O += P V (P fp16) ----
        #pragma unroll
        for (int kk = 0; kk < 4; kk++) {
            uint32_t ph[4];
            __half2 p0 = __floats2half2_rn(s[2 * kk][0],     s[2 * kk][1]);
            __half2 p1 = __floats2half2_rn(s[2 * kk][2],     s[2 * kk][3]);
            __half2 p2 = __floats2half2_rn(s[2 * kk + 1][0], s[2 * kk + 1][1]);
            __half2 p3 = __floats2half2_rn(s[2 * kk + 1][2], s[2 * kk + 1][3]);
            ph[0] = *reinterpret_cast<uint32_t*>(&p0);
            ph[1] = *reinterpret_cast<uint32_t*>(&p1);
            ph[2] = *reinterpret_cast<uint32_t*>(&p2);
            ph[3] = *reinterpret_cast<uint32_t*>(&p3);
            #pragma unroll
            for (int g2 = 0; g2 < 4; g2++) {
                uint32_t rvh[4];
                ldsm4t(rvh, s2u(&sVh[(kk * 16 + lrow) * 72 + g2 * 16 + lcol]) + offKV);
                uint32_t bh0[2] = {rvh[0], rvh[1]}, bh1[2] = {rvh[2], rvh[3]};
                mma_f16(o[g2 * 2],     ph, bh0);
                mma_f16(o[g2 * 2 + 1], ph, bh1);
            }
        }
    }

    // epilogue: reduce deferred l, normalize, write y [b,s,h,d]
    float l0 = l_r[0], l1 = l_r[1];
    l0 += __shfl_xor_sync(0xffffffffu, l0, 1);
    l0 += __shfl_xor_sync(0xffffffffu, l0, 2);
    l1 += __shfl_xor_sync(0xffffffffu, l1, 1);
    l1 += __shfl_xor_sync(0xffffffffu, l1, 2);

    int b = bh >> 4, hh = bh & 15;
    float inv0 = 1.0f / l0;
    float inv1 = 1.0f / l1;
    #pragma unroll
    for (int h2 = 0; h2 < 2; h2++) {
        int srow = q0 + w * 16 + gid + h2 * 8;
        float inv = h2 ? inv1 : inv0;
        size_t base = (((size_t)(b * SEQ + srow)) * HEADS + hh) * HD;
        #pragma unroll
        for (int j = 0; j < 8; j++) {
            float a = o[j][h2 * 2 + 0] * inv;
            float c = o[j][h2 * 2 + 1] * inv;
            __half2 h2v = __floats2half2_rn(a, c);
            int d = j * 8 + 2 * tig;
            *reinterpret_cast<uint32_t*>(&y_hi[base + d]) = *reinterpret_cast<uint32_t*>(&h2v);
        }
    }
}

// ============================ launch ============================
extern "C" void kernel_launch(void* const* d_in, const int* in_sizes, int n_in,
                              void* d_out, int out_size)
{
    const float* x        = (const float*)d_in[0];
    const float* ln_scale = (const float*)d_in[2];
    const float* ln_bias  = (const float*)d_in[3];
    const float* w_qkv    = (const float*)d_in[4];
    const float* b_qkv    = (const float*)d_in[5];
    const float* w_out    = (const float*)d_in[6];
    const float* b_out    = (const float*)d_in[7];
    float* out = (float*)d_out;

    __half *xn_hi, *wq_hi, *wo_hi, *y_hi;
    __half *qh, *kh, *vh;
    float* bq_s;
    cudaGetSymbolAddress((void**)&xn_hi, g_xn_hi);
    cudaGetSymbolAddress((void**)&wq_hi, g_wq_hi);
    cudaGetSymbolAddress((void**)&wo_hi, g_wo_hi);
    cudaGetSymbolAddress((void**)&y_hi,  g_y_hi);
    cudaGetSymbolAddress((void**)&qh, g_qh);
    cudaGetSymbolAddress((void**)&kh, g_kh);
    cudaGetSymbolAddress((void**)&vh, g_vh);
    cudaGetSymbolAddress((void**)&bq_s, g_bq_s);

    // 1. LayerNorm -> fp16
    ln_kernel<<<ROWS, 256>>>(x, ln_scale, ln_bias, xn_hi);

    // 1b. fused weight/bias prep (q-scale folded)
    prep_kernel<<<768, 256>>>(w_qkv, w_out, b_qkv, wq_hi, wo_hi, bq_s);

    int gemm_smem = 3 * GSTAGE;   // 56832

    // 2. QKV projection -> q/k/v fp16 [b,h,s,d]
    {
        cudaFuncSetAttribute(mma_gemm<0>,
                             cudaFuncAttributeMaxDynamicSharedMemorySize, gemm_smem);
        dim3 grid(QKV_N / 128, ROWS / 128);  // (24, 64)
        mma_gemm<0><<<grid, 256, gemm_smem>>>(xn_hi, wq_hi, bq_s, nullptr,
                                              ROWS, QKV_N, DIM, qh, kh, vh);
    }

    // 3. tensor-core causal flash attention (64-row CTAs, 4 CTA/SM)
    {
        int smem = (64 * 72 + 4 * KVSTRIDE) * sizeof(__half);  // 46080
        cudaFuncSetAttribute(attn_mma_kernel,
                             cudaFuncAttributeMaxDynamicSharedMemorySize, smem);
        dim3 grid(BATCH * HEADS, SEQ / 64);  // (64, 32)
        attn_mma_kernel<<<grid, 128, smem>>>(qh, kh, vh, y_hi);
    }

    // 4. output projection -> d_out
    {
        cudaFuncSetAttribute(mma_gemm<1>,
                             cudaFuncAttributeMaxDynamicSharedMemorySize, gemm_smem);
        dim3 grid(DIM / 128, ROWS / 128);    // (8, 64)
        mma_gemm<1><<<grid, 256, gemm_smem>>>(y_hi, wo_hi, b_out, out,
                                              ROWS, DIM, DIM,
                                              nullptr, nullptr, nullptr);
    }
}